// round 10
// baseline (speedup 1.0000x reference)
#include <cuda_runtime.h>
#include <cstdint>
#include <math.h>

// ---------------------------------------------------------------------------
// Problem constants
// ---------------------------------------------------------------------------
static constexpr int Bn = 32;
static constexpr int Sn = 1024;
static constexpr int En = 512;
static constexpr int Hn = 8;
static constexpr int Dn = 64;       // E / H
static constexpr int Ln = 2;
static constexpr int Mn = Bn * Sn;  // 32768 rows
static constexpr size_t ME = (size_t)Mn * En;  // 16,777,216 elements

// Scratch arena: X, Q, K, V, Attn (5 * 64MB) + PE table (2MB)
__device__ float g_buf[5 * ME + (size_t)Sn * En];

// ---------------------------------------------------------------------------
// Helpers
// ---------------------------------------------------------------------------
__device__ __forceinline__ uint64_t pack2(float lo, float hi) {
    uint64_t r;
    asm("mov.b64 %0, {%1, %2};" : "=l"(r) : "f"(lo), "f"(hi));
    return r;
}
__device__ __forceinline__ void fma2(uint64_t& d, uint64_t a, uint64_t b) {
    asm("fma.rn.f32x2 %0, %1, %2, %0;" : "+l"(d) : "l"(a), "l"(b));
}
__device__ __forceinline__ void mul2(uint64_t& d, uint64_t a, uint64_t b) {
    asm("mul.rn.f32x2 %0, %1, %2;" : "=l"(d) : "l"(a), "l"(b));
}
__device__ __forceinline__ float2 unpack2(uint64_t v) {
    float2 f;
    asm("mov.b64 {%0, %1}, %2;" : "=f"(f.x), "=f"(f.y) : "l"(v));
    return f;
}
__device__ __forceinline__ float ex2(float x) {
    float r;
    asm("ex2.approx.ftz.f32 %0, %1;" : "=f"(r) : "f"(x));
    return r;
}
__device__ __forceinline__ uint32_t smem_u32(const void* p) {
    uint32_t a;
    asm("{ .reg .u64 t; cvta.to.shared.u64 t, %1; cvt.u32.u64 %0, t; }" : "=r"(a) : "l"(p));
    return a;
}
__device__ __forceinline__ void cp16(uint32_t s, const void* g) {
    asm volatile("cp.async.cg.shared.global [%0], [%1], 16;" :: "r"(s), "l"(g));
}
__device__ __forceinline__ void cp_commit() {
    asm volatile("cp.async.commit_group;");
}
__device__ __forceinline__ void cp_wait_all() {
    asm volatile("cp.async.wait_group 0;");
}

// ---------------------------------------------------------------------------
// Positional encoding table
// ---------------------------------------------------------------------------
__global__ void pe_kernel(float* __restrict__ pe) {
    int idx = blockIdx.x * blockDim.x + threadIdx.x;
    if (idx >= Sn * En) return;
    int s = idx >> 9;
    int e = idx & 511;
    float i2 = (float)(e & ~1);
    float div = __expf(i2 * (-9.210340371976184f / (float)En));
    float a = (float)s * div;
    pe[idx] = (e & 1) ? cosf(a) : sinf(a);
}

// ---------------------------------------------------------------------------
// Embedding gather + PE add
// ---------------------------------------------------------------------------
__global__ void embed_kernel(const int* __restrict__ tok,
                             const float* __restrict__ table,
                             const float* __restrict__ pe,
                             float* __restrict__ x) {
    int idx4 = blockIdx.x * blockDim.x + threadIdx.x;
    if (idx4 >= Mn * (En / 4)) return;
    int row = idx4 >> 7;
    int d4  = idx4 & 127;
    int s   = row & (Sn - 1);
    int t   = tok[row];
    float4 tv = ((const float4*)table)[(size_t)t * 128 + d4];
    float4 pv = ((const float4*)pe)[(size_t)s * 128 + d4];
    float4 o;
    o.x = tv.x + pv.x; o.y = tv.y + pv.y; o.z = tv.z + pv.z; o.w = tv.w + pv.w;
    ((float4*)x)[idx4] = o;
}

// ---------------------------------------------------------------------------
// SGEMM (R5 proven): cp.async double-buffered, FFMA2 inner, 128x128x16.
// ---------------------------------------------------------------------------
template <bool RELU_RES>
__global__ __launch_bounds__(256, 2)
void gemm512(const float* __restrict__ A, const float* __restrict__ W,
             const float* __restrict__ bias, const float* __restrict__ res,
             float* __restrict__ C) {
    __shared__ float As[2][128 * 16];
    __shared__ float Bs[2][16 * 128];
    const int tid = threadIdx.x;
    const int tx = tid & 15;
    const int ty = tid >> 4;
    const int row0 = blockIdx.y * 128;
    const int col0 = blockIdx.x * 128;
    const uint32_t aS = smem_u32(As[0]);
    const uint32_t bS = smem_u32(Bs[0]);

    uint64_t acc2[8][4];
#pragma unroll
    for (int i = 0; i < 8; ++i)
#pragma unroll
        for (int j = 0; j < 4; ++j) acc2[i][j] = 0ull;

    auto issue = [&](int c) {
        const int buf = c & 1;
        const uint32_t ab = aS + buf * (128 * 16 * 4);
        const uint32_t bb = bS + buf * (16 * 128 * 4);
        const float* Ag = A + (size_t)row0 * En + c * 16;
        const float* Wg = W + (size_t)(c * 16) * En + col0;
#pragma unroll
        for (int i = 0; i < 2; ++i) {
            int idx = tid + i * 256;
            int m = idx >> 2, k4 = idx & 3;
            cp16(ab + (m * 16 + k4 * 4) * 4, Ag + (size_t)m * En + k4 * 4);
        }
#pragma unroll
        for (int i = 0; i < 2; ++i) {
            int idx = tid + i * 256;
            int kk = idx >> 5, n4 = idx & 31;
            cp16(bb + (kk * 128 + n4 * 4) * 4, Wg + (size_t)kk * En + n4 * 4);
        }
        cp_commit();
    };

    issue(0);
    for (int c = 0; c < 32; ++c) {
        cp_wait_all();
        __syncthreads();
        if (c < 31) issue(c + 1);
        const float* as_ = As[c & 1];
        const float* bs_ = Bs[c & 1];
#pragma unroll
        for (int kk = 0; kk < 16; ++kk) {
            ulonglong2 b01 = *(const ulonglong2*)&bs_[kk * 128 + tx * 4];
            ulonglong2 b23 = *(const ulonglong2*)&bs_[kk * 128 + 64 + tx * 4];
#pragma unroll
            for (int i = 0; i < 8; ++i) {
                float a = as_[(ty * 8 + i) * 16 + kk];
                uint64_t av = pack2(a, a);
                fma2(acc2[i][0], av, b01.x);
                fma2(acc2[i][1], av, b01.y);
                fma2(acc2[i][2], av, b23.x);
                fma2(acc2[i][3], av, b23.y);
            }
        }
    }

    float4 bi0 = *(const float4*)&bias[col0 + tx * 4];
    float4 bi1 = *(const float4*)&bias[col0 + 64 + tx * 4];
#pragma unroll
    for (int i = 0; i < 8; ++i) {
        int m = row0 + ty * 8 + i;
        size_t off0 = (size_t)m * En + col0 + tx * 4;
        size_t off1 = off0 + 64;
        float2 p0 = unpack2(acc2[i][0]);
        float2 p1 = unpack2(acc2[i][1]);
        float2 p2 = unpack2(acc2[i][2]);
        float2 p3 = unpack2(acc2[i][3]);
        float4 v0, v1;
        v0.x = p0.x + bi0.x; v0.y = p0.y + bi0.y;
        v0.z = p1.x + bi0.z; v0.w = p1.y + bi0.w;
        v1.x = p2.x + bi1.x; v1.y = p2.y + bi1.y;
        v1.z = p3.x + bi1.z; v1.w = p3.y + bi1.w;
        if (RELU_RES) {
            float4 r0 = *(const float4*)&res[off0];
            float4 r1 = *(const float4*)&res[off1];
            v0.x = r0.x + fmaxf(v0.x, 0.f); v0.y = r0.y + fmaxf(v0.y, 0.f);
            v0.z = r0.z + fmaxf(v0.z, 0.f); v0.w = r0.w + fmaxf(v0.w, 0.f);
            v1.x = r1.x + fmaxf(v1.x, 0.f); v1.y = r1.y + fmaxf(v1.y, 0.f);
            v1.z = r1.z + fmaxf(v1.z, 0.f); v1.w = r1.w + fmaxf(v1.w, 0.f);
        }
        *(float4*)&C[off0] = v0;
        *(float4*)&C[off1] = v1;
    }
}

// ---------------------------------------------------------------------------
// GEMM-structured causal flash attention (R9 design, PV dim bug fixed).
// Block: 128 q-rows of one (b,h), 256 threads.  tx=tid&3 (16 keys/dims),
// ty=tid>>2 (2 rows).  S = Q@K^T as tiled GEMM (Qs[dim][row], Kt[dim][key]),
// softmax in registers (rows span 4 lanes -> 2-shfl reductions), P restaged
// via smem, PV as a second GEMM vs natural Vs.  2 blocks/SM (16 warps).
// ---------------------------------------------------------------------------
static constexpr int QB = 128;                 // q rows per block
static constexpr int KB = 64;                  // keys per tile
static constexpr int QPAD = 132;               // Qs row pad (floats)
static constexpr int KPAD = 68;                // Kt/Ps row pad (floats)
static constexpr int OFF_Q = 0;                            // Qs[64][132]
static constexpr int OFF_K = OFF_Q + Dn * QPAD;            // Kt[64][68]
static constexpr int OFF_V = OFF_K + Dn * KPAD;            // Vs[64][64]
static constexpr int OFF_P = OFF_V + KB * Dn;              // Ps[128][68]
static constexpr int ATT_SMEM = (OFF_P + QB * KPAD) * 4;   // 102400 B
static constexpr float SC2 = 0.18033688011112042f;  // (1/8) * log2(e)

__global__ __launch_bounds__(256, 2)
void attn_kernel(const float* __restrict__ Q, const float* __restrict__ Kg,
                 const float* __restrict__ Vg, float* __restrict__ Og) {
    extern __shared__ float sm[];
    float* Qs = sm + OFF_Q;
    float* Kt = sm + OFF_K;
    float* Vs = sm + OFF_V;
    float* Ps = sm + OFF_P;
    const uint32_t sV = smem_u32(Vs);

    const int b = blockIdx.z, h = blockIdx.y, qt = blockIdx.x;
    const int tid = threadIdx.x;
    const int tx = tid & 3;        // key/dim group (16 wide)
    const int ty = tid >> 2;       // row pair (0..63)

    // ---- stage Q transposed: Qs[dim][row] ----
    {
        int row = tid >> 1;
        int dbase = (tid & 1) * 32;
        const float* Qg = Q + ((size_t)(b * Sn + qt * QB + row)) * En + h * Dn + dbase;
#pragma unroll
        for (int j = 0; j < 8; ++j) {
            float4 v = *(const float4*)(Qg + 4 * j);
            Qs[(dbase + 4 * j + 0) * QPAD + row] = v.x;
            Qs[(dbase + 4 * j + 1) * QPAD + row] = v.y;
            Qs[(dbase + 4 * j + 2) * QPAD + row] = v.z;
            Qs[(dbase + 4 * j + 3) * QPAD + row] = v.w;
        }
    }

    uint64_t O2[2][8];
#pragma unroll
    for (int i = 0; i < 2; ++i)
#pragma unroll
        for (int p = 0; p < 8; ++p) O2[i][p] = 0ull;
    float m[2] = {-1e30f, -1e30f}, l[2] = {0.f, 0.f};

    const int nkt = 2 * qt + 2;    // 64-key tiles up to & incl. diagonal

    for (int kt = 0; kt < nkt; ++kt) {
        // ---- stage V (cp.async, natural) + K (ldg->sts transposed) ----
        {
            size_t base = ((size_t)(b * Sn + kt * KB)) * En + h * Dn;
#pragma unroll
            for (int i2 = 0; i2 < 4; ++i2) {
                int idx = tid + i2 * 256;
                int key = idx >> 4, d4 = idx & 15;
                cp16(sV + (key * Dn + d4 * 4) * 4, Vg + base + (size_t)key * En + d4 * 4);
            }
            cp_commit();
            int key = tid >> 2;
            int dbase = (tid & 3) * 4;
            const float* Kr = Kg + base + (size_t)key * En;
#pragma unroll
            for (int j = 0; j < 4; ++j) {
                float4 v = *(const float4*)(Kr + dbase + 16 * j);
                Kt[(dbase + 16 * j + 0) * KPAD + key] = v.x;
                Kt[(dbase + 16 * j + 1) * KPAD + key] = v.y;
                Kt[(dbase + 16 * j + 2) * KPAD + key] = v.z;
                Kt[(dbase + 16 * j + 3) * KPAD + key] = v.w;
            }
            cp_wait_all();
        }
        __syncthreads();

        // ---- S = Q @ K^T : rows {2ty, 2ty+1} x keys {16tx..16tx+15} ----
        uint64_t acc[2][8];
#pragma unroll
        for (int i = 0; i < 2; ++i)
#pragma unroll
            for (int p = 0; p < 8; ++p) acc[i][p] = 0ull;

#pragma unroll 8
        for (int d = 0; d < Dn; ++d) {
            float2 aa = *(const float2*)&Qs[d * QPAD + ty * 2];
            const ulonglong2* kb = (const ulonglong2*)&Kt[d * KPAD + tx * 16];
            ulonglong2 b01 = kb[0], b23 = kb[1], b45 = kb[2], b67 = kb[3];
            uint64_t a0 = pack2(aa.x, aa.x);
            uint64_t a1 = pack2(aa.y, aa.y);
            fma2(acc[0][0], a0, b01.x); fma2(acc[0][1], a0, b01.y);
            fma2(acc[0][2], a0, b23.x); fma2(acc[0][3], a0, b23.y);
            fma2(acc[0][4], a0, b45.x); fma2(acc[0][5], a0, b45.y);
            fma2(acc[0][6], a0, b67.x); fma2(acc[0][7], a0, b67.y);
            fma2(acc[1][0], a1, b01.x); fma2(acc[1][1], a1, b01.y);
            fma2(acc[1][2], a1, b23.x); fma2(acc[1][3], a1, b23.y);
            fma2(acc[1][4], a1, b45.x); fma2(acc[1][5], a1, b45.y);
            fma2(acc[1][6], a1, b67.x); fma2(acc[1][7], a1, b67.y);
        }

        // ---- softmax (rows span lanes tx=0..3: 2-shfl reductions) ----
        const int moff = (kt - 2 * qt) * KB;   // >=0 only on diagonal tiles
        const bool dm = (kt >= 2 * qt);
#pragma unroll
        for (int i = 0; i < 2; ++i) {
            const int rl = ty * 2 + i;
            float sc[16];
#pragma unroll
            for (int p = 0; p < 8; ++p) {
                float2 v = unpack2(acc[i][p]);
                sc[2 * p]     = v.x * SC2;
                sc[2 * p + 1] = v.y * SC2;
            }
            if (dm) {
#pragma unroll
                for (int j = 0; j < 16; ++j)
                    if (moff + tx * 16 + j > rl) sc[j] = -1e30f;
            }
            float tm = sc[0];
#pragma unroll
            for (int j = 1; j < 16; ++j) tm = fmaxf(tm, sc[j]);
            tm = fmaxf(tm, __shfl_xor_sync(0xffffffffu, tm, 1));
            tm = fmaxf(tm, __shfl_xor_sync(0xffffffffu, tm, 2));
            float mn = fmaxf(m[i], tm);
            float corr = ex2(m[i] - mn);
            m[i] = mn;
            float ls = 0.f;
#pragma unroll
            for (int j = 0; j < 16; ++j) {
                sc[j] = ex2(sc[j] - mn);
                ls += sc[j];
            }
            ls += __shfl_xor_sync(0xffffffffu, ls, 1);
            ls += __shfl_xor_sync(0xffffffffu, ls, 2);
            l[i] = l[i] * corr + ls;
            uint64_t c2 = pack2(corr, corr);
#pragma unroll
            for (int p = 0; p < 8; ++p) mul2(O2[i][p], O2[i][p], c2);
#pragma unroll
            for (int u = 0; u < 4; ++u) {
                float4 pv = make_float4(sc[4 * u], sc[4 * u + 1], sc[4 * u + 2], sc[4 * u + 3]);
                *(float4*)&Ps[rl * KPAD + tx * 16 + 4 * u] = pv;
            }
        }
        __syncthreads();

        // ---- O += P @ V : dims {16tx..16tx+15} (ALL 8 accumulators) ----
#pragma unroll 4
        for (int k0 = 0; k0 < KB; k0 += 4) {
            float pa[2][4];
            *(float4*)pa[0] = *(const float4*)&Ps[(ty * 2 + 0) * KPAD + k0];
            *(float4*)pa[1] = *(const float4*)&Ps[(ty * 2 + 1) * KPAD + k0];
#pragma unroll
            for (int j = 0; j < 4; ++j) {
                const ulonglong2* vb = (const ulonglong2*)&Vs[(k0 + j) * Dn + tx * 16];
                ulonglong2 v01 = vb[0], v23 = vb[1], v45 = vb[2], v67 = vb[3];
#pragma unroll
                for (int i = 0; i < 2; ++i) {
                    uint64_t av = pack2(pa[i][j], pa[i][j]);
                    fma2(O2[i][0], av, v01.x); fma2(O2[i][1], av, v01.y);
                    fma2(O2[i][2], av, v23.x); fma2(O2[i][3], av, v23.y);
                    fma2(O2[i][4], av, v45.x); fma2(O2[i][5], av, v45.y);
                    fma2(O2[i][6], av, v67.x); fma2(O2[i][7], av, v67.y);
                }
            }
        }
        __syncthreads();
    }

    // ---- epilogue ----
#pragma unroll
    for (int i = 0; i < 2; ++i) {
        float inv = 1.f / l[i];
        uint64_t iv = pack2(inv, inv);
        float* op = Og + ((size_t)(b * Sn + qt * QB + ty * 2 + i)) * En + h * Dn + tx * 16;
#pragma unroll
        for (int u = 0; u < 4; ++u) {
            uint64_t r0 = O2[i][2 * u], r1 = O2[i][2 * u + 1];
            mul2(r0, r0, iv);
            mul2(r1, r1, iv);
            float2 x0 = unpack2(r0), x1 = unpack2(r1);
            *(float4*)(op + 4 * u) = make_float4(x0.x, x0.y, x1.x, x1.y);
        }
    }
}

// ---------------------------------------------------------------------------
// Final head: out[m] = X[m,:] . W_out[:,0] + b_out   (warp per row)
// ---------------------------------------------------------------------------
__global__ void head_kernel(const float* __restrict__ X,
                            const float* __restrict__ Wout,
                            const float* __restrict__ bout,
                            float* __restrict__ out) {
    int gw = (blockIdx.x * blockDim.x + threadIdx.x) >> 5;
    int lane = threadIdx.x & 31;
    if (gw >= Mn) return;
    const float4* xr = (const float4*)(X + (size_t)gw * En);
    const float4* w4 = (const float4*)Wout;
    float acc = 0.f;
#pragma unroll
    for (int i = 0; i < 4; ++i) {
        float4 xv = xr[lane + i * 32];
        float4 wv = w4[lane + i * 32];
        acc += xv.x * wv.x + xv.y * wv.y + xv.z * wv.z + xv.w * wv.w;
    }
#pragma unroll
    for (int o = 16; o > 0; o >>= 1)
        acc += __shfl_xor_sync(0xffffffffu, acc, o);
    if (lane == 0) out[gw] = acc + bout[0];
}

// ---------------------------------------------------------------------------
// Launch
// ---------------------------------------------------------------------------
extern "C" void kernel_launch(void* const* d_in, const int* in_sizes, int n_in,
                              void* d_out, int out_size) {
    const int*   tok   = (const int*)d_in[0];
    const float* table = (const float*)d_in[1];
    const float* Wq    = (const float*)d_in[2];
    const float* bq    = (const float*)d_in[3];
    const float* Wk    = (const float*)d_in[4];
    const float* bk    = (const float*)d_in[5];
    const float* Wv    = (const float*)d_in[6];
    const float* bv    = (const float*)d_in[7];
    const float* Wo    = (const float*)d_in[8];
    const float* bo    = (const float*)d_in[9];
    const float* Wout  = (const float*)d_in[10];
    const float* bout  = (const float*)d_in[11];
    float* out = (float*)d_out;

    void* base = nullptr;
    cudaGetSymbolAddress(&base, g_buf);   // not a stream op: capture-safe
    float* X  = (float*)base;
    float* Qb = X + ME;
    float* Kb = X + 2 * ME;
    float* Vb = X + 3 * ME;
    float* Ab = X + 4 * ME;
    float* PE = X + 5 * ME;

    static bool attr_done = false;
    if (!attr_done) {
        cudaFuncSetAttribute(attn_kernel, cudaFuncAttributeMaxDynamicSharedMemorySize, ATT_SMEM);
        attr_done = true;
    }

    pe_kernel<<<(Sn * En + 255) / 256, 256>>>(PE);
    embed_kernel<<<(Mn * (En / 4) + 255) / 256, 256>>>(tok, table, PE, X);

    dim3 gg(En / 128, Mn / 128);     // (4, 256)
    dim3 ag(Sn / QB, Hn, Bn);        // (8, 8, 32)
    for (int l = 0; l < Ln; ++l) {
        const float* wq = Wq + (size_t)l * En * En; const float* bql = bq + l * En;
        const float* wk = Wk + (size_t)l * En * En; const float* bkl = bk + l * En;
        const float* wv = Wv + (size_t)l * En * En; const float* bvl = bv + l * En;
        const float* wo = Wo + (size_t)l * En * En; const float* bol = bo + l * En;
        gemm512<false><<<gg, 256>>>(X,  wq, bql, nullptr, Qb);
        gemm512<false><<<gg, 256>>>(X,  wk, bkl, nullptr, Kb);
        gemm512<false><<<gg, 256>>>(X,  wv, bvl, nullptr, Vb);
        attn_kernel<<<ag, 256, ATT_SMEM>>>(Qb, Kb, Vb, Ab);
        gemm512<true><<<gg, 256>>>(Ab, wo, bol, X, X);   // X = X + relu(attn@Wo+bo)
    }
    head_kernel<<<(Mn * 32 + 255) / 256, 256>>>(X, Wout, bout, out);
}

// round 11
// speedup vs baseline: 1.3871x; 1.3871x over previous
#include <cuda_runtime.h>
#include <cstdint>
#include <math.h>

// ---------------------------------------------------------------------------
// Problem constants
// ---------------------------------------------------------------------------
static constexpr int Bn = 32;
static constexpr int Sn = 1024;
static constexpr int En = 512;
static constexpr int Hn = 8;
static constexpr int Dn = 64;       // E / H
static constexpr int Ln = 2;
static constexpr int Mn = Bn * Sn;  // 32768 rows
static constexpr size_t ME = (size_t)Mn * En;  // 16,777,216 elements

// Scratch arena: X, Q, K, V, Attn (5 * 64MB) + PE table (2MB)
__device__ float g_buf[5 * ME + (size_t)Sn * En];

// ---------------------------------------------------------------------------
// Helpers
// ---------------------------------------------------------------------------
__device__ __forceinline__ uint64_t pack2(float lo, float hi) {
    uint64_t r;
    asm("mov.b64 %0, {%1, %2};" : "=l"(r) : "f"(lo), "f"(hi));
    return r;
}
__device__ __forceinline__ void fma2(uint64_t& d, uint64_t a, uint64_t b) {
    asm("fma.rn.f32x2 %0, %1, %2, %0;" : "+l"(d) : "l"(a), "l"(b));
}
__device__ __forceinline__ void mul2(uint64_t& d, uint64_t a, uint64_t b) {
    asm("mul.rn.f32x2 %0, %1, %2;" : "=l"(d) : "l"(a), "l"(b));
}
__device__ __forceinline__ float2 unpack2(uint64_t v) {
    float2 f;
    asm("mov.b64 {%0, %1}, %2;" : "=f"(f.x), "=f"(f.y) : "l"(v));
    return f;
}
__device__ __forceinline__ float ex2(float x) {
    float r;
    asm("ex2.approx.ftz.f32 %0, %1;" : "=f"(r) : "f"(x));
    return r;
}
__device__ __forceinline__ uint32_t smem_u32(const void* p) {
    uint32_t a;
    asm("{ .reg .u64 t; cvta.to.shared.u64 t, %1; cvt.u32.u64 %0, t; }" : "=r"(a) : "l"(p));
    return a;
}
__device__ __forceinline__ void cp16(uint32_t s, const void* g) {
    asm volatile("cp.async.cg.shared.global [%0], [%1], 16;" :: "r"(s), "l"(g));
}
__device__ __forceinline__ void cp_commit() {
    asm volatile("cp.async.commit_group;");
}
__device__ __forceinline__ void cp_wait_all() {
    asm volatile("cp.async.wait_group 0;");
}
__device__ __forceinline__ void cp_wait_1() {
    asm volatile("cp.async.wait_group 1;");
}

// ---------------------------------------------------------------------------
// Positional encoding table
// ---------------------------------------------------------------------------
__global__ void pe_kernel(float* __restrict__ pe) {
    int idx = blockIdx.x * blockDim.x + threadIdx.x;
    if (idx >= Sn * En) return;
    int s = idx >> 9;
    int e = idx & 511;
    float i2 = (float)(e & ~1);
    float div = __expf(i2 * (-9.210340371976184f / (float)En));
    float a = (float)s * div;
    pe[idx] = (e & 1) ? cosf(a) : sinf(a);
}

// ---------------------------------------------------------------------------
// Embedding gather + PE add
// ---------------------------------------------------------------------------
__global__ void embed_kernel(const int* __restrict__ tok,
                             const float* __restrict__ table,
                             const float* __restrict__ pe,
                             float* __restrict__ x) {
    int idx4 = blockIdx.x * blockDim.x + threadIdx.x;
    if (idx4 >= Mn * (En / 4)) return;
    int row = idx4 >> 7;
    int d4  = idx4 & 127;
    int s   = row & (Sn - 1);
    int t   = tok[row];
    float4 tv = ((const float4*)table)[(size_t)t * 128 + d4];
    float4 pv = ((const float4*)pe)[(size_t)s * 128 + d4];
    float4 o;
    o.x = tv.x + pv.x; o.y = tv.y + pv.y; o.z = tv.z + pv.z; o.w = tv.w + pv.w;
    ((float4*)x)[idx4] = o;
}

// ---------------------------------------------------------------------------
// SGEMM v4: 3-stage cp.async pipeline, FFMA2 inner, 128x128x16 tile.
// Buffers c%3; at iter c: wait_group(1) -> chunk c resident, sync,
// issue chunk c+2 (buffer (c+2)%3, last touched at iter c-1), compute c.
// ---------------------------------------------------------------------------
template <bool RELU_RES>
__global__ __launch_bounds__(256, 2)
void gemm512(const float* __restrict__ A, const float* __restrict__ W,
             const float* __restrict__ bias, const float* __restrict__ res,
             float* __restrict__ C) {
    __shared__ float As[3][128 * 16];
    __shared__ float Bs[3][16 * 128];
    const int tid = threadIdx.x;
    const int tx = tid & 15;
    const int ty = tid >> 4;
    const int row0 = blockIdx.y * 128;
    const int col0 = blockIdx.x * 128;
    const uint32_t aS = smem_u32(As[0]);
    const uint32_t bS = smem_u32(Bs[0]);

    uint64_t acc2[8][4];
#pragma unroll
    for (int i = 0; i < 8; ++i)
#pragma unroll
        for (int j = 0; j < 4; ++j) acc2[i][j] = 0ull;

    auto issue = [&](int c) {
        const int buf = c % 3;
        const uint32_t ab = aS + buf * (128 * 16 * 4);
        const uint32_t bb = bS + buf * (16 * 128 * 4);
        const float* Ag = A + (size_t)row0 * En + c * 16;
        const float* Wg = W + (size_t)(c * 16) * En + col0;
#pragma unroll
        for (int i = 0; i < 2; ++i) {
            int idx = tid + i * 256;
            int m = idx >> 2, k4 = idx & 3;
            cp16(ab + (m * 16 + k4 * 4) * 4, Ag + (size_t)m * En + k4 * 4);
        }
#pragma unroll
        for (int i = 0; i < 2; ++i) {
            int idx = tid + i * 256;
            int kk = idx >> 5, n4 = idx & 31;
            cp16(bb + (kk * 128 + n4 * 4) * 4, Wg + (size_t)kk * En + n4 * 4);
        }
        cp_commit();
    };

    issue(0);
    issue(1);
    for (int c = 0; c < 32; ++c) {
        if (c < 31) cp_wait_1(); else cp_wait_all();
        __syncthreads();
        if (c + 2 < 32) issue(c + 2);
        const float* as_ = As[c % 3];
        const float* bs_ = Bs[c % 3];
#pragma unroll
        for (int kk = 0; kk < 16; ++kk) {
            ulonglong2 b01 = *(const ulonglong2*)&bs_[kk * 128 + tx * 4];
            ulonglong2 b23 = *(const ulonglong2*)&bs_[kk * 128 + 64 + tx * 4];
#pragma unroll
            for (int i = 0; i < 8; ++i) {
                float a = as_[(ty * 8 + i) * 16 + kk];
                uint64_t av = pack2(a, a);
                fma2(acc2[i][0], av, b01.x);
                fma2(acc2[i][1], av, b01.y);
                fma2(acc2[i][2], av, b23.x);
                fma2(acc2[i][3], av, b23.y);
            }
        }
    }

    float4 bi0 = *(const float4*)&bias[col0 + tx * 4];
    float4 bi1 = *(const float4*)&bias[col0 + 64 + tx * 4];
#pragma unroll
    for (int i = 0; i < 8; ++i) {
        int m = row0 + ty * 8 + i;
        size_t off0 = (size_t)m * En + col0 + tx * 4;
        size_t off1 = off0 + 64;
        float2 p0 = unpack2(acc2[i][0]);
        float2 p1 = unpack2(acc2[i][1]);
        float2 p2 = unpack2(acc2[i][2]);
        float2 p3 = unpack2(acc2[i][3]);
        float4 v0, v1;
        v0.x = p0.x + bi0.x; v0.y = p0.y + bi0.y;
        v0.z = p1.x + bi0.z; v0.w = p1.y + bi0.w;
        v1.x = p2.x + bi1.x; v1.y = p2.y + bi1.y;
        v1.z = p3.x + bi1.z; v1.w = p3.y + bi1.w;
        if (RELU_RES) {
            float4 r0 = *(const float4*)&res[off0];
            float4 r1 = *(const float4*)&res[off1];
            v0.x = r0.x + fmaxf(v0.x, 0.f); v0.y = r0.y + fmaxf(v0.y, 0.f);
            v0.z = r0.z + fmaxf(v0.z, 0.f); v0.w = r0.w + fmaxf(v0.w, 0.f);
            v1.x = r1.x + fmaxf(v1.x, 0.f); v1.y = r1.y + fmaxf(v1.y, 0.f);
            v1.z = r1.z + fmaxf(v1.z, 0.f); v1.w = r1.w + fmaxf(v1.w, 0.f);
        }
        *(float4*)&C[off0] = v0;
        *(float4*)&C[off1] = v1;
    }
}

// ---------------------------------------------------------------------------
// Causal flash attention (R5 structure): one thread per query row, KT=64,
// cp.async double-buffered K/V tiles, one sync per tile, exp2-domain softmax
// with MUFU ex2, score dot as 4 chains of depth 8.
// ---------------------------------------------------------------------------
static constexpr int KT = 64;
static constexpr int ATT_SMEM = 2 * 2 * KT * Dn * (int)sizeof(float);  // 65536
static constexpr float SC2 = 0.18033688011112042f;  // (1/8) * log2(e)

__global__ __launch_bounds__(128)
void attn_kernel(const float* __restrict__ Q, const float* __restrict__ Kg,
                 const float* __restrict__ Vg, float* __restrict__ Og) {
    extern __shared__ float smA[];   // [buf][K(4096) | V(4096)]
    const uint32_t sS = smem_u32(smA);
    const int b = blockIdx.z, h = blockIdx.y, qt = blockIdx.x;
    const int r = threadIdx.x;
    const int qg = qt * 128 + r;

    const ulonglong2* qp = (const ulonglong2*)(Q + ((size_t)(b * Sn + qg)) * En + h * Dn);
    uint64_t q2[32];
#pragma unroll
    for (int i = 0; i < 16; ++i) {
        ulonglong2 t = qp[i];
        q2[2 * i] = t.x; q2[2 * i + 1] = t.y;
    }
    uint64_t o2[32];
#pragma unroll
    for (int i = 0; i < 32; ++i) o2[i] = 0ull;

    float mi = -1e30f, l = 0.f;
    const int nkt = qt * 2 + 2;      // 64-key tiles up to & incl. diagonal

    auto issue_tile = [&](int kt) {
        size_t base = ((size_t)(b * Sn + kt * KT)) * En + h * Dn;
        uint32_t kd = sS + (kt & 1) * 32768;
        uint32_t vd = kd + 16384;
#pragma unroll
        for (int i = 0; i < 8; ++i) {           // 1024 cp16 each for K and V
            int idx = r + i * 128;
            int row = idx >> 4, d4 = idx & 15;
            const float* src = Kg + base + (size_t)row * En + d4 * 4;
            const float* srv = Vg + base + (size_t)row * En + d4 * 4;
            uint32_t off = (row * 64 + d4 * 4) * 4;
            cp16(kd + off, src);
            cp16(vd + off, srv);
        }
        cp_commit();
    };

    issue_tile(0);
    for (int kt = 0; kt < nkt; ++kt) {
        cp_wait_all();
        __syncthreads();
        if (kt + 1 < nkt) issue_tile(kt + 1);   // overlaps compute below

        const float* Ks = smA + (kt & 1) * 8192;
        const float* Vs = Ks + 4096;
        const bool masked = (kt >= qt * 2);     // only diagonal-straddling tiles
        const int kbase = kt * KT;

        float s[KT];
        float tmax = -1e30f;
#pragma unroll 4
        for (int j = 0; j < KT; ++j) {
            const ulonglong2* kr = (const ulonglong2*)(Ks + j * 64);
            uint64_t c0 = 0ull, c1 = 0ull, c2c = 0ull, c3 = 0ull;  // 4 chains, depth 8
#pragma unroll
            for (int d = 0; d < 8; ++d) {       // kr[0..15]: all 64 dims
                ulonglong2 kva = kr[2 * d];
                ulonglong2 kvb = kr[2 * d + 1];
                fma2(c0,  q2[4 * d],     kva.x);
                fma2(c1,  q2[4 * d + 1], kva.y);
                fma2(c2c, q2[4 * d + 2], kvb.x);
                fma2(c3,  q2[4 * d + 3], kvb.y);
            }
            float2 f0 = unpack2(c0), f1 = unpack2(c1);
            float2 f2 = unpack2(c2c), f3 = unpack2(c3);
            float sj = ((f0.x + f0.y) + (f1.x + f1.y))
                     + ((f2.x + f2.y) + (f3.x + f3.y));
            sj *= SC2;                                  // exp2 domain
            if (masked && (kbase + j > qg)) sj = -1e30f;
            s[j] = sj;
            tmax = fmaxf(tmax, sj);
        }

        float mnew = fmaxf(mi, tmax);
        float corr = ex2(mi - mnew);
        l *= corr;
        uint64_t cc = pack2(corr, corr);
#pragma unroll
        for (int d = 0; d < 32; ++d) mul2(o2[d], o2[d], cc);
#pragma unroll 4
        for (int j = 0; j < KT; ++j) {
            float p = ex2(s[j] - mnew);
            l += p;
            uint64_t p2 = pack2(p, p);
            const ulonglong2* vr = (const ulonglong2*)(Vs + j * 64);
#pragma unroll
            for (int d = 0; d < 16; ++d) {
                ulonglong2 vv = vr[d];
                fma2(o2[2 * d],     p2, vv.x);
                fma2(o2[2 * d + 1], p2, vv.y);
            }
        }
        mi = mnew;
    }

    float inv = 1.f / l;
    float4* op = (float4*)(Og + ((size_t)(b * Sn + qg)) * En + h * Dn);
#pragma unroll
    for (int i = 0; i < 16; ++i) {
        float2 lo = unpack2(o2[2 * i]);
        float2 hi = unpack2(o2[2 * i + 1]);
        float4 v;
        v.x = lo.x * inv; v.y = lo.y * inv;
        v.z = hi.x * inv; v.w = hi.y * inv;
        op[i] = v;
    }
}

// ---------------------------------------------------------------------------
// Final head: out[m] = X[m,:] . W_out[:,0] + b_out   (warp per row)
// ---------------------------------------------------------------------------
__global__ void head_kernel(const float* __restrict__ X,
                            const float* __restrict__ Wout,
                            const float* __restrict__ bout,
                            float* __restrict__ out) {
    int gw = (blockIdx.x * blockDim.x + threadIdx.x) >> 5;
    int lane = threadIdx.x & 31;
    if (gw >= Mn) return;
    const float4* xr = (const float4*)(X + (size_t)gw * En);
    const float4* w4 = (const float4*)Wout;
    float acc = 0.f;
#pragma unroll
    for (int i = 0; i < 4; ++i) {
        float4 xv = xr[lane + i * 32];
        float4 wv = w4[lane + i * 32];
        acc += xv.x * wv.x + xv.y * wv.y + xv.z * wv.z + xv.w * wv.w;
    }
#pragma unroll
    for (int o = 16; o > 0; o >>= 1)
        acc += __shfl_xor_sync(0xffffffffu, acc, o);
    if (lane == 0) out[gw] = acc + bout[0];
}

// ---------------------------------------------------------------------------
// Launch
// ---------------------------------------------------------------------------
extern "C" void kernel_launch(void* const* d_in, const int* in_sizes, int n_in,
                              void* d_out, int out_size) {
    const int*   tok   = (const int*)d_in[0];
    const float* table = (const float*)d_in[1];
    const float* Wq    = (const float*)d_in[2];
    const float* bq    = (const float*)d_in[3];
    const float* Wk    = (const float*)d_in[4];
    const float* bk    = (const float*)d_in[5];
    const float* Wv    = (const float*)d_in[6];
    const float* bv    = (const float*)d_in[7];
    const float* Wo    = (const float*)d_in[8];
    const float* bo    = (const float*)d_in[9];
    const float* Wout  = (const float*)d_in[10];
    const float* bout  = (const float*)d_in[11];
    float* out = (float*)d_out;

    void* base = nullptr;
    cudaGetSymbolAddress(&base, g_buf);   // not a stream op: capture-safe
    float* X  = (float*)base;
    float* Qb = X + ME;
    float* Kb = X + 2 * ME;
    float* Vb = X + 3 * ME;
    float* Ab = X + 4 * ME;
    float* PE = X + 5 * ME;

    static bool attr_done = false;
    if (!attr_done) {
        cudaFuncSetAttribute(attn_kernel, cudaFuncAttributeMaxDynamicSharedMemorySize, ATT_SMEM);
        attr_done = true;
    }

    pe_kernel<<<(Sn * En + 255) / 256, 256>>>(PE);
    embed_kernel<<<(Mn * (En / 4) + 255) / 256, 256>>>(tok, table, PE, X);

    dim3 gg(En / 128, Mn / 128);   // (4, 256)
    dim3 ag(Sn / 128, Hn, Bn);     // (8, 8, 32)
    for (int l = 0; l < Ln; ++l) {
        const float* wq = Wq + (size_t)l * En * En; const float* bql = bq + l * En;
        const float* wk = Wk + (size_t)l * En * En; const float* bkl = bk + l * En;
        const float* wv = Wv + (size_t)l * En * En; const float* bvl = bv + l * En;
        const float* wo = Wo + (size_t)l * En * En; const float* bol = bo + l * En;
        gemm512<false><<<gg, 256>>>(X,  wq, bql, nullptr, Qb);
        gemm512<false><<<gg, 256>>>(X,  wk, bkl, nullptr, Kb);
        gemm512<false><<<gg, 256>>>(X,  wv, bvl, nullptr, Vb);
        attn_kernel<<<ag, 128, ATT_SMEM>>>(Qb, Kb, Vb, Ab);
        gemm512<true><<<gg, 256>>>(Ab, wo, bol, X, X);   // X = X + relu(attn@Wo+bo)
    }
    head_kernel<<<(Mn * 32 + 255) / 256, 256>>>(X, Wout, bout, out);
}